// round 1
// baseline (speedup 1.0000x reference)
#include <cuda_runtime.h>
#include <math.h>
#include <stdint.h>

#define B_  16
#define S_  784
#define D_  768
#define H_  12
#define DH_ 64
#define M_  (B_ * S_)          // 12544

// ---------------- scratch (device globals: allocation-free) ----------------
__device__ float g_q [B_ * S_ * D_];
__device__ float g_k [B_ * S_ * D_];
__device__ float g_v [B_ * S_ * D_];
__device__ float g_ao[B_ * S_ * D_];

// ---------------- GEMM: C[M,N] = A[M,K] @ W[N,K]^T + bias[N] ----------------
#define GM 128
#define GN 64
#define GK 16

__global__ void __launch_bounds__(256)
gemm_bias_kernel(const float* __restrict__ A, const float* __restrict__ W,
                 const float* __restrict__ bias, float* __restrict__ C,
                 int M, int N, int K)
{
    __shared__ float As[GK][GM];
    __shared__ float Ws[GK][GN + 4];

    const int tid = threadIdx.x;
    const int tx  = tid & 15;   // n direction (16 x 4 = 64)
    const int ty  = tid >> 4;   // m direction (16 x 8 = 128)
    const int bm  = blockIdx.y * GM;
    const int bn  = blockIdx.x * GN;

    const float* Ap = A + (size_t)bm * K;
    const float* Wp = W + (size_t)bn * K;

    float acc[8][4];
#pragma unroll
    for (int i = 0; i < 8; i++)
#pragma unroll
        for (int j = 0; j < 4; j++) acc[i][j] = 0.0f;

    for (int k0 = 0; k0 < K; k0 += GK) {
        // load A tile: 128 rows x 16 k  (512 float4, 2 per thread)
#pragma unroll
        for (int it = 0; it < 2; it++) {
            int f  = tid + it * 256;
            int m  = f >> 2;
            int kq = (f & 3) * 4;
            float4 v = *(const float4*)(Ap + (size_t)m * K + k0 + kq);
            As[kq + 0][m] = v.x;
            As[kq + 1][m] = v.y;
            As[kq + 2][m] = v.z;
            As[kq + 3][m] = v.w;
        }
        // load W tile: 64 rows x 16 k (256 float4, 1 per thread)
        {
            int n  = tid >> 2;
            int kq = (tid & 3) * 4;
            float4 v = *(const float4*)(Wp + (size_t)n * K + k0 + kq);
            Ws[kq + 0][n] = v.x;
            Ws[kq + 1][n] = v.y;
            Ws[kq + 2][n] = v.z;
            Ws[kq + 3][n] = v.w;
        }
        __syncthreads();

#pragma unroll
        for (int kk = 0; kk < GK; kk++) {
            float a[8], w[4];
            *(float4*)&a[0] = *(const float4*)&As[kk][ty * 8];
            *(float4*)&a[4] = *(const float4*)&As[kk][ty * 8 + 4];
            *(float4*)&w[0] = *(const float4*)&Ws[kk][tx * 4];
#pragma unroll
            for (int i = 0; i < 8; i++)
#pragma unroll
                for (int j = 0; j < 4; j++)
                    acc[i][j] += a[i] * w[j];
        }
        __syncthreads();
    }

    float b4[4];
    *(float4*)b4 = *(const float4*)(bias + bn + tx * 4);

#pragma unroll
    for (int i = 0; i < 8; i++) {
        float4 o;
        o.x = acc[i][0] + b4[0];
        o.y = acc[i][1] + b4[1];
        o.z = acc[i][2] + b4[2];
        o.w = acc[i][3] + b4[3];
        *(float4*)(C + (size_t)(bm + ty * 8 + i) * N + bn + tx * 4) = o;
    }
}

// ---------------- Flash attention with fused RoPE ----------------
#define BQ   64
#define BK   64
#define PADR 68   // row stride (floats) for 64-wide tiles
#define NKT  ((S_ + BK - 1) / BK)   // 13

__global__ void __launch_bounds__(256)
attn_kernel(const float* __restrict__ Q, const float* __restrict__ K,
            const float* __restrict__ V, const float* __restrict__ rope,
            float* __restrict__ O)
{
    extern __shared__ float smem[];
    float* Qs = smem;                 // [BQ][PADR]
    float* Ks = Qs + BQ * PADR;       // [BK][PADR]
    float* Vs = Ks + BK * PADR;       // [BK][PADR]
    float* Ps = Vs + BK * PADR;       // [BQ][PADR]

    const int tid = threadIdx.x;
    const int tx  = tid & 15;
    const int ty  = tid >> 4;
    const int qt  = blockIdx.x;
    const int h   = blockIdx.y;
    const int b   = blockIdx.z;
    const int q0  = qt * BQ;

    const float* Qb = Q + (size_t)b * S_ * D_ + h * DH_;
    const float* Kb = K + (size_t)b * S_ * D_ + h * DH_;
    const float* Vb = V + (size_t)b * S_ * D_ + h * DH_;
    const float* Rb = rope + (size_t)b * S_ * DH_;

    // ---- load Q tile with RoPE ----
    for (int p = tid; p < BQ * 32; p += 256) {
        int r  = p >> 5;
        int pc = (p & 31) * 2;
        int s  = q0 + r;
        float v0 = 0.f, v1 = 0.f;
        if (s < S_) {
            float2 e   = *(const float2*)(Qb + (size_t)s * D_ + pc);
            float2 ang = *(const float2*)(Rb + (size_t)s * DH_ + pc);
            float c0, s0, c1, s1;
            sincosf(ang.x, &s0, &c0);
            sincosf(ang.y, &s1, &c1);
            v0 = e.x * c0 - e.y * s0;
            v1 = e.y * c1 + e.x * s1;
        }
        Qs[r * PADR + pc]     = v0;
        Qs[r * PADR + pc + 1] = v1;
    }

    float m_prev[4], lsum[4], o_acc[4][4];
#pragma unroll
    for (int i = 0; i < 4; i++) {
        m_prev[i] = -1e30f;
        lsum[i]   = 0.f;
#pragma unroll
        for (int j = 0; j < 4; j++) o_acc[i][j] = 0.f;
    }
    __syncthreads();

    const float scale = 0.125f;  // DH^-0.5

    for (int kt = 0; kt < NKT; kt++) {
        const int k0 = kt * BK;

        // ---- load K (RoPE) + V tiles ----
        for (int p = tid; p < BK * 32; p += 256) {
            int r  = p >> 5;
            int pc = (p & 31) * 2;
            int s  = k0 + r;
            float kv0 = 0.f, kv1 = 0.f, vv0 = 0.f, vv1 = 0.f;
            if (s < S_) {
                float2 e   = *(const float2*)(Kb + (size_t)s * D_ + pc);
                float2 ang = *(const float2*)(Rb + (size_t)s * DH_ + pc);
                float c0, s0, c1, s1;
                sincosf(ang.x, &s0, &c0);
                sincosf(ang.y, &s1, &c1);
                kv0 = e.x * c0 - e.y * s0;
                kv1 = e.y * c1 + e.x * s1;
                float2 vv = *(const float2*)(Vb + (size_t)s * D_ + pc);
                vv0 = vv.x; vv1 = vv.y;
            }
            Ks[r * PADR + pc]     = kv0;
            Ks[r * PADR + pc + 1] = kv1;
            Vs[r * PADR + pc]     = vv0;
            Vs[r * PADR + pc + 1] = vv1;
        }
        __syncthreads();

        // ---- scores: S = Q @ K^T ----
        float sacc[4][4];
#pragma unroll
        for (int i = 0; i < 4; i++)
#pragma unroll
            for (int j = 0; j < 4; j++) sacc[i][j] = 0.f;

#pragma unroll 4
        for (int kd = 0; kd < DH_; kd += 4) {
            float4 qv[4], kv[4];
#pragma unroll
            for (int i = 0; i < 4; i++)
                qv[i] = *(const float4*)&Qs[(ty * 4 + i) * PADR + kd];
#pragma unroll
            for (int j = 0; j < 4; j++)
                kv[j] = *(const float4*)&Ks[(tx * 4 + j) * PADR + kd];
#pragma unroll
            for (int i = 0; i < 4; i++)
#pragma unroll
                for (int j = 0; j < 4; j++)
                    sacc[i][j] += qv[i].x * kv[j].x + qv[i].y * kv[j].y +
                                  qv[i].z * kv[j].z + qv[i].w * kv[j].w;
        }

        // mask + scale
#pragma unroll
        for (int j = 0; j < 4; j++) {
            bool valid = (k0 + tx * 4 + j) < S_;
#pragma unroll
            for (int i = 0; i < 4; i++)
                sacc[i][j] = valid ? sacc[i][j] * scale : -1e30f;
        }

        // ---- online softmax (row groups of 16 lanes) ----
#pragma unroll
        for (int i = 0; i < 4; i++) {
            float mx = fmaxf(fmaxf(sacc[i][0], sacc[i][1]),
                             fmaxf(sacc[i][2], sacc[i][3]));
            mx = fmaxf(mx, __shfl_xor_sync(0xffffffffu, mx, 8));
            mx = fmaxf(mx, __shfl_xor_sync(0xffffffffu, mx, 4));
            mx = fmaxf(mx, __shfl_xor_sync(0xffffffffu, mx, 2));
            mx = fmaxf(mx, __shfl_xor_sync(0xffffffffu, mx, 1));

            float mn   = fmaxf(m_prev[i], mx);
            float corr = expf(m_prev[i] - mn);
            float rs   = 0.f;
#pragma unroll
            for (int j = 0; j < 4; j++) {
                float pv = expf(sacc[i][j] - mn);
                sacc[i][j] = pv;
                rs += pv;
            }
            rs += __shfl_xor_sync(0xffffffffu, rs, 8);
            rs += __shfl_xor_sync(0xffffffffu, rs, 4);
            rs += __shfl_xor_sync(0xffffffffu, rs, 2);
            rs += __shfl_xor_sync(0xffffffffu, rs, 1);

            lsum[i] = lsum[i] * corr + rs;
#pragma unroll
            for (int j = 0; j < 4; j++) o_acc[i][j] *= corr;
            m_prev[i] = mn;
        }

        // ---- write P tile ----
        __syncthreads();   // prior PV reads of Ps done
#pragma unroll
        for (int i = 0; i < 4; i++)
            *(float4*)&Ps[(ty * 4 + i) * PADR + tx * 4] =
                make_float4(sacc[i][0], sacc[i][1], sacc[i][2], sacc[i][3]);
        __syncthreads();

        // ---- O += P @ V ----
#pragma unroll 4
        for (int kk = 0; kk < BK; kk += 4) {
            float4 pv[4], vv[4];
#pragma unroll
            for (int i = 0; i < 4; i++)
                pv[i] = *(const float4*)&Ps[(ty * 4 + i) * PADR + kk];
#pragma unroll
            for (int j = 0; j < 4; j++)
                vv[j] = *(const float4*)&Vs[(kk + j) * PADR + tx * 4];
#pragma unroll
            for (int i = 0; i < 4; i++) {
                o_acc[i][0] += pv[i].x * vv[0].x + pv[i].y * vv[1].x +
                               pv[i].z * vv[2].x + pv[i].w * vv[3].x;
                o_acc[i][1] += pv[i].x * vv[0].y + pv[i].y * vv[1].y +
                               pv[i].z * vv[2].y + pv[i].w * vv[3].y;
                o_acc[i][2] += pv[i].x * vv[0].z + pv[i].y * vv[1].z +
                               pv[i].z * vv[2].z + pv[i].w * vv[3].z;
                o_acc[i][3] += pv[i].x * vv[0].w + pv[i].y * vv[1].w +
                               pv[i].z * vv[2].w + pv[i].w * vv[3].w;
            }
        }
        __syncthreads();   // before next tile overwrites Ks/Vs
    }

    // ---- normalize + write (transposed to [B,S,D]) ----
#pragma unroll
    for (int i = 0; i < 4; i++) {
        int qg = q0 + ty * 4 + i;
        if (qg < S_) {
            float inv = 1.0f / lsum[i];
            float4 o;
            o.x = o_acc[i][0] * inv;
            o.y = o_acc[i][1] * inv;
            o.z = o_acc[i][2] * inv;
            o.w = o_acc[i][3] * inv;
            *(float4*)(O + ((size_t)b * S_ + qg) * D_ + h * DH_ + tx * 4) = o;
        }
    }
}

// ---------------- launch ----------------
extern "C" void kernel_launch(void* const* d_in, const int* in_sizes, int n_in,
                              void* d_out, int out_size)
{
    const float* hs   = (const float*)d_in[0];
    const float* rope = (const float*)d_in[1];
    const float* wq   = (const float*)d_in[2];
    const float* bq   = (const float*)d_in[3];
    const float* wk   = (const float*)d_in[4];
    const float* bk   = (const float*)d_in[5];
    const float* wv   = (const float*)d_in[6];
    const float* bv   = (const float*)d_in[7];
    const float* wo   = (const float*)d_in[8];
    const float* bo   = (const float*)d_in[9];
    float* out = (float*)d_out;

    float *gq, *gk, *gv, *gao;
    cudaGetSymbolAddress((void**)&gq,  g_q);
    cudaGetSymbolAddress((void**)&gk,  g_k);
    cudaGetSymbolAddress((void**)&gv,  g_v);
    cudaGetSymbolAddress((void**)&gao, g_ao);

    const int attn_smem = 4 * BQ * PADR * (int)sizeof(float);  // 69632 B
    cudaFuncSetAttribute(attn_kernel,
                         cudaFuncAttributeMaxDynamicSharedMemorySize, attn_smem);

    dim3 gblk(256);
    dim3 ggrid(D_ / GN, M_ / GM);   // (12, 98)

    gemm_bias_kernel<<<ggrid, gblk>>>(hs, wq, bq, gq, M_, D_, D_);
    gemm_bias_kernel<<<ggrid, gblk>>>(hs, wk, bk, gk, M_, D_, D_);
    gemm_bias_kernel<<<ggrid, gblk>>>(hs, wv, bv, gv, M_, D_, D_);

    dim3 agrid(NKT, H_, B_);        // (13, 12, 16)
    attn_kernel<<<agrid, gblk, attn_smem>>>(gq, gk, gv, rope, gao);

    gemm_bias_kernel<<<ggrid, gblk>>>(gao, wo, bo, out, M_, D_, D_);
}

// round 3
// speedup vs baseline: 1.3096x; 1.3096x over previous
#include <cuda_runtime.h>
#include <math.h>
#include <stdint.h>

#define B_  16
#define S_  784
#define D_  768
#define H_  12
#define DH_ 64
#define M_  (B_ * S_)          // 12544

// ---------------- scratch (device globals: allocation-free) ----------------
__device__ float g_q [B_ * S_ * D_];
__device__ float g_k [B_ * S_ * D_];
__device__ float g_v [B_ * S_ * D_];
__device__ float g_ao[B_ * S_ * D_];

// =====================================================================
// tf32 tensor-core GEMM: C[M,N] = A[M,K] @ W[N,K]^T + bias[N]
// Block tile 128x64, K-tile 32. 8 warps: 4(m) x 2(n), warp tile 32x32.
// Per warp: 2 m16 tiles x 4 n8 tiles of mma.sync.m16n8k8.tf32.
// fp32 -> tf32 conversion happens during global->smem staging.
// =====================================================================
#define TBM 128
#define TBN 64
#define TBK 32
#define TPAD 36   // smem row stride in floats (conflict-free for frag gathers)

__global__ void __launch_bounds__(256)
gemm_tf32_kernel(const float* __restrict__ A, const float* __restrict__ W,
                 const float* __restrict__ bias, float* __restrict__ C,
                 int M, int N, int K)
{
    __shared__ float As[TBM][TPAD];
    __shared__ float Ws[TBN][TPAD];

    const int tid  = threadIdx.x;
    const int lane = tid & 31;
    const int warp = tid >> 5;
    const int wm   = (warp >> 1) * 32;   // warp m offset in block
    const int wn   = (warp & 1)  * 32;   // warp n offset in block
    const int bm   = blockIdx.y * TBM;
    const int bn   = blockIdx.x * TBN;

    const int g = lane >> 2;   // group id (0..7)
    const int t = lane & 3;    // thread-in-group (0..3)

    float acc[2][4][4];
#pragma unroll
    for (int mt = 0; mt < 2; mt++)
#pragma unroll
        for (int nt = 0; nt < 4; nt++)
#pragma unroll
            for (int r = 0; r < 4; r++) acc[mt][nt][r] = 0.0f;

    for (int k0 = 0; k0 < K; k0 += TBK) {
        // ---- stage A tile (128 x 32): 1024 float4 / 256 thr = 4 each ----
#pragma unroll
        for (int it = 0; it < 4; it++) {
            int f  = tid + it * 256;
            int r  = f >> 3;
            int kq = (f & 7) * 4;
            float4 v = *(const float4*)(A + (size_t)(bm + r) * K + k0 + kq);
            uint32_t cx, cy, cz, cw;
            asm("cvt.rna.tf32.f32 %0, %1;" : "=r"(cx) : "f"(v.x));
            asm("cvt.rna.tf32.f32 %0, %1;" : "=r"(cy) : "f"(v.y));
            asm("cvt.rna.tf32.f32 %0, %1;" : "=r"(cz) : "f"(v.z));
            asm("cvt.rna.tf32.f32 %0, %1;" : "=r"(cw) : "f"(v.w));
            As[r][kq + 0] = __uint_as_float(cx);
            As[r][kq + 1] = __uint_as_float(cy);
            As[r][kq + 2] = __uint_as_float(cz);
            As[r][kq + 3] = __uint_as_float(cw);
        }
        // ---- stage W tile (64 x 32): 512 float4 / 256 thr = 2 each ----
#pragma unroll
        for (int it = 0; it < 2; it++) {
            int f  = tid + it * 256;
            int r  = f >> 3;
            int kq = (f & 7) * 4;
            float4 v = *(const float4*)(W + (size_t)(bn + r) * K + k0 + kq);
            uint32_t cx, cy, cz, cw;
            asm("cvt.rna.tf32.f32 %0, %1;" : "=r"(cx) : "f"(v.x));
            asm("cvt.rna.tf32.f32 %0, %1;" : "=r"(cy) : "f"(v.y));
            asm("cvt.rna.tf32.f32 %0, %1;" : "=r"(cz) : "f"(v.z));
            asm("cvt.rna.tf32.f32 %0, %1;" : "=r"(cw) : "f"(v.w));
            Ws[r][kq + 0] = __uint_as_float(cx);
            Ws[r][kq + 1] = __uint_as_float(cy);
            Ws[r][kq + 2] = __uint_as_float(cz);
            Ws[r][kq + 3] = __uint_as_float(cw);
        }
        __syncthreads();

#pragma unroll
        for (int kk = 0; kk < TBK; kk += 8) {
            uint32_t a[2][4];
#pragma unroll
            for (int mt = 0; mt < 2; mt++) {
                int r0 = wm + mt * 16 + g;
                a[mt][0] = __float_as_uint(As[r0    ][kk + t    ]);
                a[mt][1] = __float_as_uint(As[r0 + 8][kk + t    ]);
                a[mt][2] = __float_as_uint(As[r0    ][kk + t + 4]);
                a[mt][3] = __float_as_uint(As[r0 + 8][kk + t + 4]);
            }
            uint32_t b[4][2];
#pragma unroll
            for (int nt = 0; nt < 4; nt++) {
                int n0 = wn + nt * 8 + g;
                b[nt][0] = __float_as_uint(Ws[n0][kk + t    ]);
                b[nt][1] = __float_as_uint(Ws[n0][kk + t + 4]);
            }
#pragma unroll
            for (int mt = 0; mt < 2; mt++)
#pragma unroll
                for (int nt = 0; nt < 4; nt++) {
                    asm volatile(
                        "mma.sync.aligned.m16n8k8.row.col.f32.tf32.tf32.f32 "
                        "{%0,%1,%2,%3}, {%4,%5,%6,%7}, {%8,%9}, {%0,%1,%2,%3};"
                        : "+f"(acc[mt][nt][0]), "+f"(acc[mt][nt][1]),
                          "+f"(acc[mt][nt][2]), "+f"(acc[mt][nt][3])
                        : "r"(a[mt][0]), "r"(a[mt][1]), "r"(a[mt][2]), "r"(a[mt][3]),
                          "r"(b[nt][0]), "r"(b[nt][1]));
                }
        }
        __syncthreads();
    }

    // ---- epilogue: bias add + store ----
#pragma unroll
    for (int mt = 0; mt < 2; mt++) {
#pragma unroll
        for (int nt = 0; nt < 4; nt++) {
            int row0 = bm + wm + mt * 16 + g;
            int col  = bn + wn + nt * 8 + t * 2;
            float2 bb = *(const float2*)(bias + col);
            float2 o0, o1;
            o0.x = acc[mt][nt][0] + bb.x;
            o0.y = acc[mt][nt][1] + bb.y;
            o1.x = acc[mt][nt][2] + bb.x;
            o1.y = acc[mt][nt][3] + bb.y;
            *(float2*)(C + (size_t)row0 * N + col)       = o0;
            *(float2*)(C + (size_t)(row0 + 8) * N + col) = o1;
        }
    }
}

// ---------------- Flash attention with fused RoPE ----------------
#define BQ   64
#define BK   64
#define PADR 68   // row stride (floats) for 64-wide tiles
#define NKT  ((S_ + BK - 1) / BK)   // 13

__global__ void __launch_bounds__(256)
attn_kernel(const float* __restrict__ Q, const float* __restrict__ K,
            const float* __restrict__ V, const float* __restrict__ rope,
            float* __restrict__ O)
{
    extern __shared__ float smem[];
    float* Qs = smem;                 // [BQ][PADR]
    float* Ks = Qs + BQ * PADR;       // [BK][PADR]
    float* Vs = Ks + BK * PADR;       // [BK][PADR]
    float* Ps = Vs + BK * PADR;       // [BQ][PADR]

    const int tid = threadIdx.x;
    const int tx  = tid & 15;
    const int ty  = tid >> 4;
    const int qt  = blockIdx.x;
    const int h   = blockIdx.y;
    const int b   = blockIdx.z;
    const int q0  = qt * BQ;

    const float* Qb = Q + (size_t)b * S_ * D_ + h * DH_;
    const float* Kb = K + (size_t)b * S_ * D_ + h * DH_;
    const float* Vb = V + (size_t)b * S_ * D_ + h * DH_;
    const float* Rb = rope + (size_t)b * S_ * DH_;

    // ---- load Q tile with RoPE ----
    for (int p = tid; p < BQ * 32; p += 256) {
        int r  = p >> 5;
        int pc = (p & 31) * 2;
        int s  = q0 + r;
        float v0 = 0.f, v1 = 0.f;
        if (s < S_) {
            float2 e   = *(const float2*)(Qb + (size_t)s * D_ + pc);
            float2 ang = *(const float2*)(Rb + (size_t)s * DH_ + pc);
            float c0, s0, c1, s1;
            sincosf(ang.x, &s0, &c0);
            sincosf(ang.y, &s1, &c1);
            v0 = e.x * c0 - e.y * s0;
            v1 = e.y * c1 + e.x * s1;
        }
        Qs[r * PADR + pc]     = v0;
        Qs[r * PADR + pc + 1] = v1;
    }

    float m_prev[4], lsum[4], o_acc[4][4];
#pragma unroll
    for (int i = 0; i < 4; i++) {
        m_prev[i] = -1e30f;
        lsum[i]   = 0.f;
#pragma unroll
        for (int j = 0; j < 4; j++) o_acc[i][j] = 0.f;
    }
    __syncthreads();

    const float scale = 0.125f;  // DH^-0.5

    for (int kt = 0; kt < NKT; kt++) {
        const int k0 = kt * BK;

        // ---- load K (RoPE) + V tiles ----
        for (int p = tid; p < BK * 32; p += 256) {
            int r  = p >> 5;
            int pc = (p & 31) * 2;
            int s  = k0 + r;
            float kv0 = 0.f, kv1 = 0.f, vv0 = 0.f, vv1 = 0.f;
            if (s < S_) {
                float2 e   = *(const float2*)(Kb + (size_t)s * D_ + pc);
                float2 ang = *(const float2*)(Rb + (size_t)s * DH_ + pc);
                float c0, s0, c1, s1;
                sincosf(ang.x, &s0, &c0);
                sincosf(ang.y, &s1, &c1);
                kv0 = e.x * c0 - e.y * s0;
                kv1 = e.y * c1 + e.x * s1;
                float2 vv = *(const float2*)(Vb + (size_t)s * D_ + pc);
                vv0 = vv.x; vv1 = vv.y;
            }
            Ks[r * PADR + pc]     = kv0;
            Ks[r * PADR + pc + 1] = kv1;
            Vs[r * PADR + pc]     = vv0;
            Vs[r * PADR + pc + 1] = vv1;
        }
        __syncthreads();

        // ---- scores: S = Q @ K^T ----
        float sacc[4][4];
#pragma unroll
        for (int i = 0; i < 4; i++)
#pragma unroll
            for (int j = 0; j < 4; j++) sacc[i][j] = 0.f;

#pragma unroll 4
        for (int kd = 0; kd < DH_; kd += 4) {
            float4 qv[4], kv[4];
#pragma unroll
            for (int i = 0; i < 4; i++)
                qv[i] = *(const float4*)&Qs[(ty * 4 + i) * PADR + kd];
#pragma unroll
            for (int j = 0; j < 4; j++)
                kv[j] = *(const float4*)&Ks[(tx * 4 + j) * PADR + kd];
#pragma unroll
            for (int i = 0; i < 4; i++)
#pragma unroll
                for (int j = 0; j < 4; j++)
                    sacc[i][j] += qv[i].x * kv[j].x + qv[i].y * kv[j].y +
                                  qv[i].z * kv[j].z + qv[i].w * kv[j].w;
        }

        // mask + scale
#pragma unroll
        for (int j = 0; j < 4; j++) {
            bool valid = (k0 + tx * 4 + j) < S_;
#pragma unroll
            for (int i = 0; i < 4; i++)
                sacc[i][j] = valid ? sacc[i][j] * scale : -1e30f;
        }

        // ---- online softmax (row groups of 16 lanes) ----
#pragma unroll
        for (int i = 0; i < 4; i++) {
            float mx = fmaxf(fmaxf(sacc[i][0], sacc[i][1]),
                             fmaxf(sacc[i][2], sacc[i][3]));
            mx = fmaxf(mx, __shfl_xor_sync(0xffffffffu, mx, 8));
            mx = fmaxf(mx, __shfl_xor_sync(0xffffffffu, mx, 4));
            mx = fmaxf(mx, __shfl_xor_sync(0xffffffffu, mx, 2));
            mx = fmaxf(mx, __shfl_xor_sync(0xffffffffu, mx, 1));

            float mn   = fmaxf(m_prev[i], mx);
            float corr = expf(m_prev[i] - mn);
            float rs   = 0.f;
#pragma unroll
            for (int j = 0; j < 4; j++) {
                float pv = expf(sacc[i][j] - mn);
                sacc[i][j] = pv;
                rs += pv;
            }
            rs += __shfl_xor_sync(0xffffffffu, rs, 8);
            rs += __shfl_xor_sync(0xffffffffu, rs, 4);
            rs += __shfl_xor_sync(0xffffffffu, rs, 2);
            rs += __shfl_xor_sync(0xffffffffu, rs, 1);

            lsum[i] = lsum[i] * corr + rs;
#pragma unroll
            for (int j = 0; j < 4; j++) o_acc[i][j] *= corr;
            m_prev[i] = mn;
        }

        // ---- write P tile ----
        __syncthreads();   // prior PV reads of Ps done
#pragma unroll
        for (int i = 0; i < 4; i++)
            *(float4*)&Ps[(ty * 4 + i) * PADR + tx * 4] =
                make_float4(sacc[i][0], sacc[i][1], sacc[i][2], sacc[i][3]);
        __syncthreads();

        // ---- O += P @ V ----
#pragma unroll 4
        for (int kk = 0; kk < BK; kk += 4) {
            float4 pv[4], vv[4];
#pragma unroll
            for (int i = 0; i < 4; i++)
                pv[i] = *(const float4*)&Ps[(ty * 4 + i) * PADR + kk];
#pragma unroll
            for (int j = 0; j < 4; j++)
                vv[j] = *(const float4*)&Vs[(kk + j) * PADR + tx * 4];
#pragma unroll
            for (int i = 0; i < 4; i++) {
                o_acc[i][0] += pv[i].x * vv[0].x + pv[i].y * vv[1].x +
                               pv[i].z * vv[2].x + pv[i].w * vv[3].x;
                o_acc[i][1] += pv[i].x * vv[0].y + pv[i].y * vv[1].y +
                               pv[i].z * vv[2].y + pv[i].w * vv[3].y;
                o_acc[i][2] += pv[i].x * vv[0].z + pv[i].y * vv[1].z +
                               pv[i].z * vv[2].z + pv[i].w * vv[3].z;
                o_acc[i][3] += pv[i].x * vv[0].w + pv[i].y * vv[1].w +
                               pv[i].z * vv[2].w + pv[i].w * vv[3].w;
            }
        }
        __syncthreads();   // before next tile overwrites Ks/Vs
    }

    // ---- normalize + write (transposed to [B,S,D]) ----
#pragma unroll
    for (int i = 0; i < 4; i++) {
        int qg = q0 + ty * 4 + i;
        if (qg < S_) {
            float inv = 1.0f / lsum[i];
            float4 o;
            o.x = o_acc[i][0] * inv;
            o.y = o_acc[i][1] * inv;
            o.z = o_acc[i][2] * inv;
            o.w = o_acc[i][3] * inv;
            *(float4*)(O + ((size_t)b * S_ + qg) * D_ + h * DH_ + tx * 4) = o;
        }
    }
}

// ---------------- launch ----------------
extern "C" void kernel_launch(void* const* d_in, const int* in_sizes, int n_in,
                              void* d_out, int out_size)
{
    const float* hs   = (const float*)d_in[0];
    const float* rope = (const float*)d_in[1];
    const float* wq   = (const float*)d_in[2];
    const float* bq   = (const float*)d_in[3];
    const float* wk   = (const float*)d_in[4];
    const float* bk   = (const float*)d_in[5];
    const float* wv   = (const float*)d_in[6];
    const float* bv   = (const float*)d_in[7];
    const float* wo   = (const float*)d_in[8];
    const float* bo   = (const float*)d_in[9];
    float* out = (float*)d_out;

    float *gq, *gk, *gv, *gao;
    cudaGetSymbolAddress((void**)&gq,  g_q);
    cudaGetSymbolAddress((void**)&gk,  g_k);
    cudaGetSymbolAddress((void**)&gv,  g_v);
    cudaGetSymbolAddress((void**)&gao, g_ao);

    const int attn_smem = 4 * BQ * PADR * (int)sizeof(float);  // 69632 B
    cudaFuncSetAttribute(attn_kernel,
                         cudaFuncAttributeMaxDynamicSharedMemorySize, attn_smem);

    dim3 gblk(256);
    dim3 ggrid(D_ / TBN, M_ / TBM);   // (12, 98)

    gemm_tf32_kernel<<<ggrid, gblk>>>(hs, wq, bq, gq, M_, D_, D_);
    gemm_tf32_kernel<<<ggrid, gblk>>>(hs, wk, bk, gk, M_, D_, D_);
    gemm_tf32_kernel<<<ggrid, gblk>>>(hs, wv, bv, gv, M_, D_, D_);

    dim3 agrid(NKT, H_, B_);          // (13, 12, 16)
    attn_kernel<<<agrid, gblk, attn_smem>>>(gq, gk, gv, rope, gao);

    gemm_tf32_kernel<<<ggrid, gblk>>>(gao, wo, bo, out, M_, D_, D_);
}

// round 4
// speedup vs baseline: 3.3246x; 2.5386x over previous
#include <cuda_runtime.h>
#include <math.h>
#include <stdint.h>

#define B_  16
#define S_  784
#define D_  768
#define H_  12
#define DH_ 64
#define M_  (B_ * S_)          // 12544

// ---------------- scratch (device globals: allocation-free) ----------------
__device__ float g_q [B_ * S_ * D_];
__device__ float g_k [B_ * S_ * D_];
__device__ float g_v [B_ * S_ * D_];
__device__ float g_ao[B_ * S_ * D_];

__device__ __forceinline__ float to_tf32(float x) {
    uint32_t u;
    asm("cvt.rna.tf32.f32 %0, %1;" : "=r"(u) : "f"(x));
    return __uint_as_float(u);
}

// =====================================================================
// tf32 tensor-core GEMM: C[M,N] = A[M,K] @ W[N,K]^T + bias[N]
// =====================================================================
#define TBM 128
#define TBN 64
#define TBK 32
#define TPAD 36

__global__ void __launch_bounds__(256)
gemm_tf32_kernel(const float* __restrict__ A, const float* __restrict__ W,
                 const float* __restrict__ bias, float* __restrict__ C,
                 int M, int N, int K)
{
    __shared__ float As[TBM][TPAD];
    __shared__ float Ws[TBN][TPAD];

    const int tid  = threadIdx.x;
    const int lane = tid & 31;
    const int warp = tid >> 5;
    const int wm   = (warp >> 1) * 32;
    const int wn   = (warp & 1)  * 32;
    const int bm   = blockIdx.y * TBM;
    const int bn   = blockIdx.x * TBN;

    const int g = lane >> 2;
    const int t = lane & 3;

    float acc[2][4][4];
#pragma unroll
    for (int mt = 0; mt < 2; mt++)
#pragma unroll
        for (int nt = 0; nt < 4; nt++)
#pragma unroll
            for (int r = 0; r < 4; r++) acc[mt][nt][r] = 0.0f;

    for (int k0 = 0; k0 < K; k0 += TBK) {
#pragma unroll
        for (int it = 0; it < 4; it++) {
            int f  = tid + it * 256;
            int r  = f >> 3;
            int kq = (f & 7) * 4;
            float4 v = *(const float4*)(A + (size_t)(bm + r) * K + k0 + kq);
            As[r][kq + 0] = to_tf32(v.x);
            As[r][kq + 1] = to_tf32(v.y);
            As[r][kq + 2] = to_tf32(v.z);
            As[r][kq + 3] = to_tf32(v.w);
        }
#pragma unroll
        for (int it = 0; it < 2; it++) {
            int f  = tid + it * 256;
            int r  = f >> 3;
            int kq = (f & 7) * 4;
            float4 v = *(const float4*)(W + (size_t)(bn + r) * K + k0 + kq);
            Ws[r][kq + 0] = to_tf32(v.x);
            Ws[r][kq + 1] = to_tf32(v.y);
            Ws[r][kq + 2] = to_tf32(v.z);
            Ws[r][kq + 3] = to_tf32(v.w);
        }
        __syncthreads();

#pragma unroll
        for (int kk = 0; kk < TBK; kk += 8) {
            uint32_t a[2][4];
#pragma unroll
            for (int mt = 0; mt < 2; mt++) {
                int r0 = wm + mt * 16 + g;
                a[mt][0] = __float_as_uint(As[r0    ][kk + t    ]);
                a[mt][1] = __float_as_uint(As[r0 + 8][kk + t    ]);
                a[mt][2] = __float_as_uint(As[r0    ][kk + t + 4]);
                a[mt][3] = __float_as_uint(As[r0 + 8][kk + t + 4]);
            }
            uint32_t b[4][2];
#pragma unroll
            for (int nt = 0; nt < 4; nt++) {
                int n0 = wn + nt * 8 + g;
                b[nt][0] = __float_as_uint(Ws[n0][kk + t    ]);
                b[nt][1] = __float_as_uint(Ws[n0][kk + t + 4]);
            }
#pragma unroll
            for (int mt = 0; mt < 2; mt++)
#pragma unroll
                for (int nt = 0; nt < 4; nt++) {
                    asm volatile(
                        "mma.sync.aligned.m16n8k8.row.col.f32.tf32.tf32.f32 "
                        "{%0,%1,%2,%3}, {%4,%5,%6,%7}, {%8,%9}, {%0,%1,%2,%3};"
                        : "+f"(acc[mt][nt][0]), "+f"(acc[mt][nt][1]),
                          "+f"(acc[mt][nt][2]), "+f"(acc[mt][nt][3])
                        : "r"(a[mt][0]), "r"(a[mt][1]), "r"(a[mt][2]), "r"(a[mt][3]),
                          "r"(b[nt][0]), "r"(b[nt][1]));
                }
        }
        __syncthreads();
    }

#pragma unroll
    for (int mt = 0; mt < 2; mt++) {
#pragma unroll
        for (int nt = 0; nt < 4; nt++) {
            int row0 = bm + wm + mt * 16 + g;
            int col  = bn + wn + nt * 8 + t * 2;
            float2 bb = *(const float2*)(bias + col);
            float2 o0, o1;
            o0.x = acc[mt][nt][0] + bb.x;
            o0.y = acc[mt][nt][1] + bb.y;
            o1.x = acc[mt][nt][2] + bb.x;
            o1.y = acc[mt][nt][3] + bb.y;
            *(float2*)(C + (size_t)row0 * N + col)       = o0;
            *(float2*)(C + (size_t)(row0 + 8) * N + col) = o1;
        }
    }
}

// =====================================================================
// RoPE applied in place to Q and K (one pass, before attention).
// rope angles are per (b, s, dh) — shared across heads.
// =====================================================================
__global__ void __launch_bounds__(256)
rope_kernel(float* __restrict__ q, float* __restrict__ k,
            const float* __restrict__ rope)
{
    size_t idx = (size_t)blockIdx.x * 256 + threadIdx.x;   // over B*S*D/2 pairs
    if (idx >= (size_t)B_ * S_ * D_ / 2) return;
    int    pair = (int)(idx % (D_ / 2));    // 0..383
    size_t bs   = idx / (D_ / 2);           // b*S + s
    int h = pair >> 5;                      // head
    int p = pair & 31;                      // dh pair 0..31

    float2 ang = *(const float2*)(rope + bs * DH_ + p * 2);
    float c0, s0, c1, s1;
    sincosf(ang.x, &s0, &c0);
    sincosf(ang.y, &s1, &c1);

    size_t off = bs * D_ + h * DH_ + p * 2;
    float2 qv = *(float2*)(q + off);
    float2 kv = *(float2*)(k + off);
    float2 qo, ko;
    qo.x = qv.x * c0 - qv.y * s0;
    qo.y = qv.y * c1 + qv.x * s1;
    ko.x = kv.x * c0 - kv.y * s0;
    ko.y = kv.y * c1 + kv.x * s1;
    *(float2*)(q + off) = qo;
    *(float2*)(k + off) = ko;
}

// =====================================================================
// Tensor-core flash attention (tf32 mma for QK^T and PV).
// Block: 128 threads = 4 warps; warp w owns m16 rows w*16..w*16+15.
// BQ = BK = 64, DH = 64. Smem tiles stride 72 (conflict-free gathers).
// =====================================================================
#define APAD 72
#define NKT  ((S_ + 63) / 64)   // 13

__global__ void __launch_bounds__(128)
attn_mma_kernel(const float* __restrict__ Q, const float* __restrict__ K,
                const float* __restrict__ V, float* __restrict__ O)
{
    extern __shared__ float smem[];
    float* Qs = smem;                  // [64][APAD]
    float* Ks = Qs + 64 * APAD;
    float* Vs = Ks + 64 * APAD;
    float* Ps = Vs + 64 * APAD;

    const int tid  = threadIdx.x;
    const int lane = tid & 31;
    const int warp = tid >> 5;
    const int g    = lane >> 2;    // 0..7
    const int t    = lane & 3;     // 0..3
    const int wr   = warp * 16;    // warp row base

    const int q0 = blockIdx.x * 64;
    const int h  = blockIdx.y;
    const int b  = blockIdx.z;

    const float* Qb = Q + (size_t)b * S_ * D_ + h * DH_;
    const float* Kb = K + (size_t)b * S_ * D_ + h * DH_;
    const float* Vb = V + (size_t)b * S_ * D_ + h * DH_;

    // ---- stage Q tile (tf32) ----
    for (int p = tid; p < 64 * 16; p += 128) {
        int r = p >> 4, c = (p & 15) * 4;
        int s = q0 + r;
        float4 v = make_float4(0.f, 0.f, 0.f, 0.f);
        if (s < S_) v = *(const float4*)(Qb + (size_t)s * D_ + c);
        Qs[r * APAD + c + 0] = to_tf32(v.x);
        Qs[r * APAD + c + 1] = to_tf32(v.y);
        Qs[r * APAD + c + 2] = to_tf32(v.z);
        Qs[r * APAD + c + 3] = to_tf32(v.w);
    }

    float o_acc[8][4];
#pragma unroll
    for (int nt = 0; nt < 8; nt++)
#pragma unroll
        for (int r = 0; r < 4; r++) o_acc[nt][r] = 0.f;
    float m_prev[2] = {-1e30f, -1e30f};
    float lsum[2]   = {0.f, 0.f};

    const float scale = 0.125f;

    for (int kt = 0; kt < NKT; kt++) {
        const int k0 = kt * 64;

        // ---- stage K, V tiles (tf32) ----
        for (int p = tid; p < 64 * 16; p += 128) {
            int r = p >> 4, c = (p & 15) * 4;
            int s = k0 + r;
            float4 kv = make_float4(0.f, 0.f, 0.f, 0.f);
            float4 vv = make_float4(0.f, 0.f, 0.f, 0.f);
            if (s < S_) {
                kv = *(const float4*)(Kb + (size_t)s * D_ + c);
                vv = *(const float4*)(Vb + (size_t)s * D_ + c);
            }
            Ks[r * APAD + c + 0] = to_tf32(kv.x);
            Ks[r * APAD + c + 1] = to_tf32(kv.y);
            Ks[r * APAD + c + 2] = to_tf32(kv.z);
            Ks[r * APAD + c + 3] = to_tf32(kv.w);
            Vs[r * APAD + c + 0] = to_tf32(vv.x);
            Vs[r * APAD + c + 1] = to_tf32(vv.y);
            Vs[r * APAD + c + 2] = to_tf32(vv.z);
            Vs[r * APAD + c + 3] = to_tf32(vv.w);
        }
        __syncthreads();

        // ---- S = Q K^T  (m16 x n64, k = DH = 64) ----
        float s_acc[8][4];
#pragma unroll
        for (int nt = 0; nt < 8; nt++)
#pragma unroll
            for (int r = 0; r < 4; r++) s_acc[nt][r] = 0.f;

#pragma unroll
        for (int kc = 0; kc < 8; kc++) {
            const int kk = kc * 8;
            uint32_t a0 = __float_as_uint(Qs[(wr + g    ) * APAD + kk + t    ]);
            uint32_t a1 = __float_as_uint(Qs[(wr + g + 8) * APAD + kk + t    ]);
            uint32_t a2 = __float_as_uint(Qs[(wr + g    ) * APAD + kk + t + 4]);
            uint32_t a3 = __float_as_uint(Qs[(wr + g + 8) * APAD + kk + t + 4]);
#pragma unroll
            for (int nt = 0; nt < 8; nt++) {
                uint32_t b0 = __float_as_uint(Ks[(nt * 8 + g) * APAD + kk + t    ]);
                uint32_t b1 = __float_as_uint(Ks[(nt * 8 + g) * APAD + kk + t + 4]);
                asm volatile(
                    "mma.sync.aligned.m16n8k8.row.col.f32.tf32.tf32.f32 "
                    "{%0,%1,%2,%3}, {%4,%5,%6,%7}, {%8,%9}, {%0,%1,%2,%3};"
                    : "+f"(s_acc[nt][0]), "+f"(s_acc[nt][1]),
                      "+f"(s_acc[nt][2]), "+f"(s_acc[nt][3])
                    : "r"(a0), "r"(a1), "r"(a2), "r"(a3), "r"(b0), "r"(b1));
            }
        }

        // ---- scale + mask ----
#pragma unroll
        for (int nt = 0; nt < 8; nt++) {
            int c0 = k0 + nt * 8 + 2 * t;
#pragma unroll
            for (int r = 0; r < 4; r++) {
                int col = c0 + (r & 1);
                s_acc[nt][r] = (col < S_) ? s_acc[nt][r] * scale : -1e30f;
            }
        }

        // ---- online softmax (rows g and g+8; quad shuffles) ----
#pragma unroll
        for (int half = 0; half < 2; half++) {
            float mx = -1e30f;
#pragma unroll
            for (int nt = 0; nt < 8; nt++) {
                mx = fmaxf(mx, s_acc[nt][2 * half]);
                mx = fmaxf(mx, s_acc[nt][2 * half + 1]);
            }
            mx = fmaxf(mx, __shfl_xor_sync(0xffffffffu, mx, 1));
            mx = fmaxf(mx, __shfl_xor_sync(0xffffffffu, mx, 2));

            float mn   = fmaxf(m_prev[half], mx);
            float corr = __expf(m_prev[half] - mn);
            float rs   = 0.f;
#pragma unroll
            for (int nt = 0; nt < 8; nt++) {
                float p0 = __expf(s_acc[nt][2 * half]     - mn);
                float p1 = __expf(s_acc[nt][2 * half + 1] - mn);
                s_acc[nt][2 * half]     = p0;
                s_acc[nt][2 * half + 1] = p1;
                rs += p0 + p1;
            }
            rs += __shfl_xor_sync(0xffffffffu, rs, 1);
            rs += __shfl_xor_sync(0xffffffffu, rs, 2);

            lsum[half]  = lsum[half] * corr + rs;
            m_prev[half] = mn;
#pragma unroll
            for (int nt = 0; nt < 8; nt++) {
                o_acc[nt][2 * half]     *= corr;
                o_acc[nt][2 * half + 1] *= corr;
            }
        }

        // ---- P -> smem (tf32), own rows only ----
#pragma unroll
        for (int nt = 0; nt < 8; nt++) {
            float2 p0, p1;
            p0.x = to_tf32(s_acc[nt][0]);
            p0.y = to_tf32(s_acc[nt][1]);
            p1.x = to_tf32(s_acc[nt][2]);
            p1.y = to_tf32(s_acc[nt][3]);
            *(float2*)&Ps[(wr + g    ) * APAD + nt * 8 + 2 * t] = p0;
            *(float2*)&Ps[(wr + g + 8) * APAD + nt * 8 + 2 * t] = p1;
        }
        __syncwarp();

        // ---- O += P V  (m16 x n64(dh), k = 64 seq) ----
#pragma unroll
        for (int kc = 0; kc < 8; kc++) {
            const int kk = kc * 8;
            uint32_t a0 = __float_as_uint(Ps[(wr + g    ) * APAD + kk + t    ]);
            uint32_t a1 = __float_as_uint(Ps[(wr + g + 8) * APAD + kk + t    ]);
            uint32_t a2 = __float_as_uint(Ps[(wr + g    ) * APAD + kk + t + 4]);
            uint32_t a3 = __float_as_uint(Ps[(wr + g + 8) * APAD + kk + t + 4]);
#pragma unroll
            for (int nt = 0; nt < 8; nt++) {
                uint32_t b0 = __float_as_uint(Vs[(kk + t    ) * APAD + nt * 8 + g]);
                uint32_t b1 = __float_as_uint(Vs[(kk + t + 4) * APAD + nt * 8 + g]);
                asm volatile(
                    "mma.sync.aligned.m16n8k8.row.col.f32.tf32.tf32.f32 "
                    "{%0,%1,%2,%3}, {%4,%5,%6,%7}, {%8,%9}, {%0,%1,%2,%3};"
                    : "+f"(o_acc[nt][0]), "+f"(o_acc[nt][1]),
                      "+f"(o_acc[nt][2]), "+f"(o_acc[nt][3])
                    : "r"(a0), "r"(a1), "r"(a2), "r"(a3), "r"(b0), "r"(b1));
            }
        }
        __syncthreads();
    }

    // ---- normalize + store [B,S,D] ----
    float inv0 = 1.0f / lsum[0];
    float inv1 = 1.0f / lsum[1];
    int r0 = q0 + wr + g;
    int r1 = r0 + 8;
#pragma unroll
    for (int nt = 0; nt < 8; nt++) {
        int col = h * DH_ + nt * 8 + 2 * t;
        if (r0 < S_) {
            float2 o;
            o.x = o_acc[nt][0] * inv0;
            o.y = o_acc[nt][1] * inv0;
            *(float2*)(O + ((size_t)b * S_ + r0) * D_ + col) = o;
        }
        if (r1 < S_) {
            float2 o;
            o.x = o_acc[nt][2] * inv1;
            o.y = o_acc[nt][3] * inv1;
            *(float2*)(O + ((size_t)b * S_ + r1) * D_ + col) = o;
        }
    }
}

// ---------------- launch ----------------
extern "C" void kernel_launch(void* const* d_in, const int* in_sizes, int n_in,
                              void* d_out, int out_size)
{
    const float* hs   = (const float*)d_in[0];
    const float* rope = (const float*)d_in[1];
    const float* wq   = (const float*)d_in[2];
    const float* bq   = (const float*)d_in[3];
    const float* wk   = (const float*)d_in[4];
    const float* bk   = (const float*)d_in[5];
    const float* wv   = (const float*)d_in[6];
    const float* bv   = (const float*)d_in[7];
    const float* wo   = (const float*)d_in[8];
    const float* bo   = (const float*)d_in[9];
    float* out = (float*)d_out;

    float *gq, *gk, *gv, *gao;
    cudaGetSymbolAddress((void**)&gq,  g_q);
    cudaGetSymbolAddress((void**)&gk,  g_k);
    cudaGetSymbolAddress((void**)&gv,  g_v);
    cudaGetSymbolAddress((void**)&gao, g_ao);

    const int attn_smem = 4 * 64 * APAD * (int)sizeof(float);  // 73728 B
    cudaFuncSetAttribute(attn_mma_kernel,
                         cudaFuncAttributeMaxDynamicSharedMemorySize, attn_smem);

    dim3 gblk(256);
    dim3 ggrid(D_ / TBN, M_ / TBM);   // (12, 98)

    gemm_tf32_kernel<<<ggrid, gblk>>>(hs, wq, bq, gq, M_, D_, D_);
    gemm_tf32_kernel<<<ggrid, gblk>>>(hs, wk, bk, gk, M_, D_, D_);
    gemm_tf32_kernel<<<ggrid, gblk>>>(hs, wv, bv, gv, M_, D_, D_);

    int rope_blocks = (int)(((size_t)B_ * S_ * D_ / 2 + 255) / 256);
    rope_kernel<<<rope_blocks, 256>>>(gq, gk, rope);

    dim3 agrid(NKT, H_, B_);          // (13, 12, 16)
    attn_mma_kernel<<<agrid, 128, attn_smem>>>(gq, gk, gv, gao);

    gemm_tf32_kernel<<<ggrid, gblk>>>(gao, wo, bo, out, M_, D_, D_);
}

// round 7
// speedup vs baseline: 4.4260x; 1.3313x over previous
#include <cuda_runtime.h>
#include <math.h>
#include <stdint.h>

#define B_  16
#define S_  784
#define D_  768
#define H_  12
#define DH_ 64
#define M_  (B_ * S_)          // 12544

// ---------------- scratch (device globals: allocation-free) ----------------
__device__ float g_q [B_ * S_ * D_];
__device__ float g_k [B_ * S_ * D_];
__device__ float g_v [B_ * S_ * D_];
__device__ float g_ao[B_ * S_ * D_];

__device__ __forceinline__ float to_tf32(float x) {
    uint32_t u;
    asm("cvt.rna.tf32.f32 %0, %1;" : "=r"(u) : "f"(x));
    return __uint_as_float(u);
}

__device__ __forceinline__ void cp_async16(void* dst, const void* src) {
    uint32_t d = (uint32_t)__cvta_generic_to_shared(dst);
    asm volatile("cp.async.cg.shared.global [%0], [%1], 16;\n" :: "r"(d), "l"(src));
}
#define CP_COMMIT() asm volatile("cp.async.commit_group;\n" ::: "memory")
#define CP_WAIT1()  asm volatile("cp.async.wait_group 1;\n" ::: "memory")

// =====================================================================
// GEMM v2: C[M,N] = A[M,K] @ W[N,K]^T + bias  (+ optional fused RoPE)
// Block 128x128, K-tile 32, 8 warps (4m x 2n), warp tile 32x64.
// cp.async double-buffered staging; fp32 bits fed to tf32 mma (truncation).
// =====================================================================
#define GTBM 128
#define GTBN 128
#define GTBK 32
#define GPAD 36
#define GBUF (GTBM * GPAD)        // floats per tile buffer (4608)
#define GNK  (D_ / GTBK)          // 24 k-tiles
#define GEMM_SMEM (4 * GBUF * (int)sizeof(float))  // 73728 B

__global__ void __launch_bounds__(256)
gemm_v2_kernel(const float* __restrict__ A, const float* __restrict__ W,
               const float* __restrict__ bias, const float* __restrict__ rope,
               float* __restrict__ C, int do_rope)
{
    extern __shared__ float sm[];
    float* Abuf = sm;               // [2][GBUF]
    float* Wbuf = sm + 2 * GBUF;    // [2][GBUF]

    const int tid  = threadIdx.x;
    const int lane = tid & 31;
    const int warp = tid >> 5;
    const int wm   = (warp >> 1) * 32;   // 0,32,64,96
    const int wn   = (warp & 1)  * 64;   // 0,64
    const int bm   = blockIdx.y * GTBM;
    const int bn   = blockIdx.x * GTBN;
    const int g    = lane >> 2;
    const int t    = lane & 3;

    const float* Ap = A + (size_t)bm * D_;
    const float* Wp = W + (size_t)bn * D_;

    float acc[2][8][4];
#pragma unroll
    for (int mt = 0; mt < 2; mt++)
#pragma unroll
        for (int nt = 0; nt < 8; nt++)
#pragma unroll
            for (int r = 0; r < 4; r++) acc[mt][nt][r] = 0.0f;

    const int r_st  = tid >> 3;          // staging row (two rows per 256-pass)
    const int kq_st = (tid & 7) * 4;     // staging k offset

    // ---- prologue: stage k-tile 0 into buffer 0 ----
#pragma unroll
    for (int it = 0; it < 4; it++) {
        int r = r_st + (it >> 1) * 64;   // covers rows 0..127 in two halves per buffer half
        int f = tid + it * 256;
        int rr = f >> 3;
        int kk = (f & 7) * 4;
        cp_async16(&Abuf[rr * GPAD + kk], Ap + (size_t)rr * D_ + kk);
    }
#pragma unroll
    for (int it = 0; it < 4; it++) {
        int f = tid + it * 256;
        int rr = f >> 3;
        int kk = (f & 7) * 4;
        cp_async16(&Wbuf[rr * GPAD + kk], Wp + (size_t)rr * D_ + kk);
    }
    CP_COMMIT();
    (void)r_st; (void)kq_st;

    for (int kt = 0; kt < GNK; kt++) {
        const int buf = kt & 1;
        // ---- stage next tile into other buffer ----
        if (kt + 1 < GNK) {
            const int k0n = (kt + 1) * GTBK;
            float* An = Abuf + (buf ^ 1) * GBUF;
            float* Wn = Wbuf + (buf ^ 1) * GBUF;
#pragma unroll
            for (int it = 0; it < 4; it++) {
                int f = tid + it * 256;
                int rr = f >> 3;
                int kk = (f & 7) * 4;
                cp_async16(&An[rr * GPAD + kk], Ap + (size_t)rr * D_ + k0n + kk);
            }
#pragma unroll
            for (int it = 0; it < 4; it++) {
                int f = tid + it * 256;
                int rr = f >> 3;
                int kk = (f & 7) * 4;
                cp_async16(&Wn[rr * GPAD + kk], Wp + (size_t)rr * D_ + k0n + kk);
            }
        }
        CP_COMMIT();
        CP_WAIT1();
        __syncthreads();

        const float* Ab = Abuf + buf * GBUF;
        const float* Wb = Wbuf + buf * GBUF;

#pragma unroll
        for (int kc = 0; kc < 4; kc++) {
            const int kk = kc * 8;
            uint32_t a[2][4];
#pragma unroll
            for (int mt = 0; mt < 2; mt++) {
                int r0 = wm + mt * 16 + g;
                a[mt][0] = __float_as_uint(Ab[(r0    ) * GPAD + kk + t    ]);
                a[mt][1] = __float_as_uint(Ab[(r0 + 8) * GPAD + kk + t    ]);
                a[mt][2] = __float_as_uint(Ab[(r0    ) * GPAD + kk + t + 4]);
                a[mt][3] = __float_as_uint(Ab[(r0 + 8) * GPAD + kk + t + 4]);
            }
#pragma unroll
            for (int nt = 0; nt < 8; nt++) {
                int n0 = wn + nt * 8 + g;
                uint32_t b0 = __float_as_uint(Wb[n0 * GPAD + kk + t    ]);
                uint32_t b1 = __float_as_uint(Wb[n0 * GPAD + kk + t + 4]);
#pragma unroll
                for (int mt = 0; mt < 2; mt++) {
                    asm volatile(
                        "mma.sync.aligned.m16n8k8.row.col.f32.tf32.tf32.f32 "
                        "{%0,%1,%2,%3}, {%4,%5,%6,%7}, {%8,%9}, {%0,%1,%2,%3};"
                        : "+f"(acc[mt][nt][0]), "+f"(acc[mt][nt][1]),
                          "+f"(acc[mt][nt][2]), "+f"(acc[mt][nt][3])
                        : "r"(a[mt][0]), "r"(a[mt][1]), "r"(a[mt][2]), "r"(a[mt][3]),
                          "r"(b0), "r"(b1));
                }
            }
        }
        __syncthreads();
    }

    // ---- epilogue: bias (+ RoPE) + store ----
#pragma unroll
    for (int mt = 0; mt < 2; mt++) {
        int row0 = bm + wm + mt * 16 + g;
#pragma unroll
        for (int nt = 0; nt < 8; nt++) {
            int col = bn + wn + nt * 8 + t * 2;
            float2 bb = *(const float2*)(bias + col);
            float x0 = acc[mt][nt][0] + bb.x;
            float y0 = acc[mt][nt][1] + bb.y;
            float x1 = acc[mt][nt][2] + bb.x;
            float y1 = acc[mt][nt][3] + bb.y;
            if (do_rope) {
                int dh = col & (DH_ - 1);
                float2 a0 = *(const float2*)(rope + (size_t)row0 * DH_ + dh);
                float2 a1 = *(const float2*)(rope + (size_t)(row0 + 8) * DH_ + dh);
                float c0, s0, c1, s1;
                __sincosf(a0.x, &s0, &c0);
                __sincosf(a0.y, &s1, &c1);
                float nx0 = x0 * c0 - y0 * s0;
                float ny0 = y0 * c1 + x0 * s1;
                __sincosf(a1.x, &s0, &c0);
                __sincosf(a1.y, &s1, &c1);
                float nx1 = x1 * c0 - y1 * s0;
                float ny1 = y1 * c1 + x1 * s1;
                x0 = nx0; y0 = ny0; x1 = nx1; y1 = ny1;
            }
            *(float2*)(C + (size_t)row0 * D_ + col)       = make_float2(x0, y0);
            *(float2*)(C + (size_t)(row0 + 8) * D_ + col) = make_float2(x1, y1);
        }
    }
}

// =====================================================================
// Tensor-core flash attention (tf32 mma for QK^T and PV) — unchanged.
// =====================================================================
#define APAD 72
#define NKT  ((S_ + 63) / 64)   // 13

__global__ void __launch_bounds__(128)
attn_mma_kernel(const float* __restrict__ Q, const float* __restrict__ K,
                const float* __restrict__ V, float* __restrict__ O)
{
    extern __shared__ float smem[];
    float* Qs = smem;                  // [64][APAD]
    float* Ks = Qs + 64 * APAD;
    float* Vs = Ks + 64 * APAD;
    float* Ps = Vs + 64 * APAD;

    const int tid  = threadIdx.x;
    const int lane = tid & 31;
    const int warp = tid >> 5;
    const int g    = lane >> 2;
    const int t    = lane & 3;
    const int wr   = warp * 16;

    const int q0 = blockIdx.x * 64;
    const int h  = blockIdx.y;
    const int b  = blockIdx.z;

    const float* Qb = Q + (size_t)b * S_ * D_ + h * DH_;
    const float* Kb = K + (size_t)b * S_ * D_ + h * DH_;
    const float* Vb = V + (size_t)b * S_ * D_ + h * DH_;

    for (int p = tid; p < 64 * 16; p += 128) {
        int r = p >> 4, c = (p & 15) * 4;
        int s = q0 + r;
        float4 v = make_float4(0.f, 0.f, 0.f, 0.f);
        if (s < S_) v = *(const float4*)(Qb + (size_t)s * D_ + c);
        Qs[r * APAD + c + 0] = to_tf32(v.x);
        Qs[r * APAD + c + 1] = to_tf32(v.y);
        Qs[r * APAD + c + 2] = to_tf32(v.z);
        Qs[r * APAD + c + 3] = to_tf32(v.w);
    }

    float o_acc[8][4];
#pragma unroll
    for (int nt = 0; nt < 8; nt++)
#pragma unroll
        for (int r = 0; r < 4; r++) o_acc[nt][r] = 0.f;
    float m_prev[2] = {-1e30f, -1e30f};
    float lsum[2]   = {0.f, 0.f};

    const float scale = 0.125f;

    for (int kt = 0; kt < NKT; kt++) {
        const int k0 = kt * 64;

        for (int p = tid; p < 64 * 16; p += 128) {
            int r = p >> 4, c = (p & 15) * 4;
            int s = k0 + r;
            float4 kv = make_float4(0.f, 0.f, 0.f, 0.f);
            float4 vv = make_float4(0.f, 0.f, 0.f, 0.f);
            if (s < S_) {
                kv = *(const float4*)(Kb + (size_t)s * D_ + c);
                vv = *(const float4*)(Vb + (size_t)s * D_ + c);
            }
            Ks[r * APAD + c + 0] = to_tf32(kv.x);
            Ks[r * APAD + c + 1] = to_tf32(kv.y);
            Ks[r * APAD + c + 2] = to_tf32(kv.z);
            Ks[r * APAD + c + 3] = to_tf32(kv.w);
            Vs[r * APAD + c + 0] = to_tf32(vv.x);
            Vs[r * APAD + c + 1] = to_tf32(vv.y);
            Vs[r * APAD + c + 2] = to_tf32(vv.z);
            Vs[r * APAD + c + 3] = to_tf32(vv.w);
        }
        __syncthreads();

        float s_acc[8][4];
#pragma unroll
        for (int nt = 0; nt < 8; nt++)
#pragma unroll
            for (int r = 0; r < 4; r++) s_acc[nt][r] = 0.f;

#pragma unroll
        for (int kc = 0; kc < 8; kc++) {
            const int kk = kc * 8;
            uint32_t a0 = __float_as_uint(Qs[(wr + g    ) * APAD + kk + t    ]);
            uint32_t a1 = __float_as_uint(Qs[(wr + g + 8) * APAD + kk + t    ]);
            uint32_t a2 = __float_as_uint(Qs[(wr + g    ) * APAD + kk + t + 4]);
            uint32_t a3 = __float_as_uint(Qs[(wr + g + 8) * APAD + kk + t + 4]);
#pragma unroll
            for (int nt = 0; nt < 8; nt++) {
                uint32_t b0 = __float_as_uint(Ks[(nt * 8 + g) * APAD + kk + t    ]);
                uint32_t b1 = __float_as_uint(Ks[(nt * 8 + g) * APAD + kk + t + 4]);
                asm volatile(
                    "mma.sync.aligned.m16n8k8.row.col.f32.tf32.tf32.f32 "
                    "{%0,%1,%2,%3}, {%4,%5,%6,%7}, {%8,%9}, {%0,%1,%2,%3};"
                    : "+f"(s_acc[nt][0]), "+f"(s_acc[nt][1]),
                      "+f"(s_acc[nt][2]), "+f"(s_acc[nt][3])
                    : "r"(a0), "r"(a1), "r"(a2), "r"(a3), "r"(b0), "r"(b1));
            }
        }

#pragma unroll
        for (int nt = 0; nt < 8; nt++) {
            int c0 = k0 + nt * 8 + 2 * t;
#pragma unroll
            for (int r = 0; r < 4; r++) {
                int col = c0 + (r & 1);
                s_acc[nt][r] = (col < S_) ? s_acc[nt][r] * scale : -1e30f;
            }
        }

#pragma unroll
        for (int half = 0; half < 2; half++) {
            float mx = -1e30f;
#pragma unroll
            for (int nt = 0; nt < 8; nt++) {
                mx = fmaxf(mx, s_acc[nt][2 * half]);
                mx = fmaxf(mx, s_acc[nt][2 * half + 1]);
            }
            mx = fmaxf(mx, __shfl_xor_sync(0xffffffffu, mx, 1));
            mx = fmaxf(mx, __shfl_xor_sync(0xffffffffu, mx, 2));

            float mn   = fmaxf(m_prev[half], mx);
            float corr = __expf(m_prev[half] - mn);
            float rs   = 0.f;
#pragma unroll
            for (int nt = 0; nt < 8; nt++) {
                float p0 = __expf(s_acc[nt][2 * half]     - mn);
                float p1 = __expf(s_acc[nt][2 * half + 1] - mn);
                s_acc[nt][2 * half]     = p0;
                s_acc[nt][2 * half + 1] = p1;
                rs += p0 + p1;
            }
            rs += __shfl_xor_sync(0xffffffffu, rs, 1);
            rs += __shfl_xor_sync(0xffffffffu, rs, 2);

            lsum[half]  = lsum[half] * corr + rs;
            m_prev[half] = mn;
#pragma unroll
            for (int nt = 0; nt < 8; nt++) {
                o_acc[nt][2 * half]     *= corr;
                o_acc[nt][2 * half + 1] *= corr;
            }
        }

#pragma unroll
        for (int nt = 0; nt < 8; nt++) {
            float2 p0, p1;
            p0.x = to_tf32(s_acc[nt][0]);
            p0.y = to_tf32(s_acc[nt][1]);
            p1.x = to_tf32(s_acc[nt][2]);
            p1.y = to_tf32(s_acc[nt][3]);
            *(float2*)&Ps[(wr + g    ) * APAD + nt * 8 + 2 * t] = p0;
            *(float2*)&Ps[(wr + g + 8) * APAD + nt * 8 + 2 * t] = p1;
        }
        __syncwarp();

#pragma unroll
        for (int kc = 0; kc < 8; kc++) {
            const int kk = kc * 8;
            uint32_t a0 = __float_as_uint(Ps[(wr + g    ) * APAD + kk + t    ]);
            uint32_t a1 = __float_as_uint(Ps[(wr + g + 8) * APAD + kk + t    ]);
            uint32_t a2 = __float_as_uint(Ps[(wr + g    ) * APAD + kk + t + 4]);
            uint32_t a3 = __float_as_uint(Ps[(wr + g + 8) * APAD + kk + t + 4]);
#pragma unroll
            for (int nt = 0; nt < 8; nt++) {
                uint32_t b0 = __float_as_uint(Vs[(kk + t    ) * APAD + nt * 8 + g]);
                uint32_t b1 = __float_as_uint(Vs[(kk + t + 4) * APAD + nt * 8 + g]);
                asm volatile(
                    "mma.sync.aligned.m16n8k8.row.col.f32.tf32.tf32.f32 "
                    "{%0,%1,%2,%3}, {%4,%5,%6,%7}, {%8,%9}, {%0,%1,%2,%3};"
                    : "+f"(o_acc[nt][0]), "+f"(o_acc[nt][1]),
                      "+f"(o_acc[nt][2]), "+f"(o_acc[nt][3])
                    : "r"(a0), "r"(a1), "r"(a2), "r"(a3), "r"(b0), "r"(b1));
            }
        }
        __syncthreads();
    }

    float inv0 = 1.0f / lsum[0];
    float inv1 = 1.0f / lsum[1];
    int r0 = q0 + wr + g;
    int r1 = r0 + 8;
#pragma unroll
    for (int nt = 0; nt < 8; nt++) {
        int col = h * DH_ + nt * 8 + 2 * t;
        if (r0 < S_) {
            float2 o;
            o.x = o_acc[nt][0] * inv0;
            o.y = o_acc[nt][1] * inv0;
            *(float2*)(O + ((size_t)b * S_ + r0) * D_ + col) = o;
        }
        if (r1 < S_) {
            float2 o;
            o.x = o_acc[nt][2] * inv1;
            o.y = o_acc[nt][3] * inv1;
            *(float2*)(O + ((size_t)b * S_ + r1) * D_ + col) = o;
        }
    }
}

// ---------------- launch ----------------
extern "C" void kernel_launch(void* const* d_in, const int* in_sizes, int n_in,
                              void* d_out, int out_size)
{
    const float* hs   = (const float*)d_in[0];
    const float* rope = (const float*)d_in[1];
    const float* wq   = (const float*)d_in[2];
    const float* bq   = (const float*)d_in[3];
    const float* wk   = (const float*)d_in[4];
    const float* bk   = (const float*)d_in[5];
    const float* wv   = (const float*)d_in[6];
    const float* bv   = (const float*)d_in[7];
    const float* wo   = (const float*)d_in[8];
    const float* bo   = (const float*)d_in[9];
    float* out = (float*)d_out;

    float *gq, *gk, *gv, *gao;
    cudaGetSymbolAddress((void**)&gq,  g_q);
    cudaGetSymbolAddress((void**)&gk,  g_k);
    cudaGetSymbolAddress((void**)&gv,  g_v);
    cudaGetSymbolAddress((void**)&gao, g_ao);

    const int attn_smem = 4 * 64 * APAD * (int)sizeof(float);  // 73728 B
    cudaFuncSetAttribute(attn_mma_kernel,
                         cudaFuncAttributeMaxDynamicSharedMemorySize, attn_smem);
    cudaFuncSetAttribute(gemm_v2_kernel,
                         cudaFuncAttributeMaxDynamicSharedMemorySize, GEMM_SMEM);

    dim3 gblk(256);
    dim3 ggrid(D_ / GTBN, M_ / GTBM);   // (6, 98)

    gemm_v2_kernel<<<ggrid, gblk, GEMM_SMEM>>>(hs, wq, bq, rope, gq, 1);
    gemm_v2_kernel<<<ggrid, gblk, GEMM_SMEM>>>(hs, wk, bk, rope, gk, 1);
    gemm_v2_kernel<<<ggrid, gblk, GEMM_SMEM>>>(hs, wv, bv, rope, gv, 0);

    dim3 agrid(NKT, H_, B_);            // (13, 12, 16)
    attn_mma_kernel<<<agrid, 128, attn_smem>>>(gq, gk, gv, gao);

    gemm_v2_kernel<<<ggrid, gblk, GEMM_SMEM>>>(gao, wo, bo, rope, out, 0);
}